// round 1
// baseline (speedup 1.0000x reference)
#include <cuda_runtime.h>
#include <math_constants.h>

// Problem constants (fixed shapes for this dataset entry)
#define B_  8
#define H_  8
#define M_  512
#define N_  512
#define DD  64
#define HID 16

// Tiling
#define BM 64
#define BN 64
#define TM 4
#define TN 8
#define NTX 8     // thread cols (each covers cols tx + 8*j)
#define NTY 16    // thread rows (each covers rows ty*4 + i)
#define THREADS 128

// Shared strides (words). Odd pads chosen for conflict-free scalar LDS.
#define QS_STRIDE 65
#define KS_STRIDE 65
#define PS_STRIDE 65
#define VS_STRIDE 64

__global__ __launch_bounds__(THREADS)
void msdpa_kernel(const float* __restrict__ q,
                  const float* __restrict__ k,
                  const float* __restrict__ v,
                  const float* __restrict__ dmat,
                  const float* __restrict__ mixW1,
                  const float* __restrict__ mixb1,
                  const float* __restrict__ mixW2,
                  const float* __restrict__ mixb2,
                  float* __restrict__ out)
{
    extern __shared__ float smem[];
    float* Qs = smem;                          // [BM][QS_STRIDE]
    float* Ks = Qs + BM * QS_STRIDE;           // [BN][KS_STRIDE]
    float* Vs = Ks + BN * KS_STRIDE;           // [BN][VS_STRIDE]
    float* Ps = Vs + BN * VS_STRIDE;           // [BM][PS_STRIDE]

    __shared__ float sW1s[HID];   // W1[:,0,:] (score channel)
    __shared__ float sW1d[HID];   // W1[:,1,:] (dmat channel)
    __shared__ float sB1[HID];
    __shared__ float sW2[HID];
    __shared__ float sB2;

    const int tid = threadIdx.x;
    const int tx  = tid & 7;      // 0..7  (column groups)
    const int ty  = tid >> 3;     // 0..15 (row groups)

    const int b  = blockIdx.z;
    const int h  = blockIdx.y;
    const int m0 = blockIdx.x * BM;

    const float* qb = q + ((size_t)(b * H_ + h) * M_ + m0) * DD;
    const float* kb = k + (size_t)(b * H_ + h) * N_ * DD;
    const float* vb = v + (size_t)(b * H_ + h) * N_ * DD;
    const float* db = dmat + ((size_t)b * M_ + m0) * N_;

    // Per-head MLP weights -> shared
    if (tid < HID) {
        sW1s[tid] = mixW1[(h * 2 + 0) * HID + tid];
        sW1d[tid] = mixW1[(h * 2 + 1) * HID + tid];
        sB1[tid]  = mixb1[h * HID + tid];
        sW2[tid]  = mixW2[h * HID + tid];
    }
    if (tid == 0) sB2 = mixb2[h];

    // Load Q tile: [BM][DD] -> Qs, padded stride (scalar stores)
    #pragma unroll
    for (int r = 0; r < 8; r++) {
        int idx = tid + r * THREADS;       // 0..1023 float4 units
        int row = idx >> 4;                // /16
        int d4  = (idx & 15) << 2;
        float4 t = *(const float4*)(qb + row * DD + d4);
        float* dst = Qs + row * QS_STRIDE + d4;
        dst[0] = t.x; dst[1] = t.y; dst[2] = t.z; dst[3] = t.w;
    }

    // Per-thread accumulators
    float Oacc[TM][TN];
    float rmax[TM], rsum[TM];
    #pragma unroll
    for (int i = 0; i < TM; i++) {
        rmax[i] = -CUDART_INF_F;
        rsum[i] = 0.0f;
        #pragma unroll
        for (int j = 0; j < TN; j++) Oacc[i][j] = 0.0f;
    }

    __syncthreads();  // Qs + weights visible

    const unsigned FULL = 0xffffffffu;

    for (int t = 0; t < N_ / BN; t++) {
        // ---- Load K,V tiles ----
        const float* kt = kb + (size_t)t * BN * DD;
        const float* vt = vb + (size_t)t * BN * DD;
        #pragma unroll
        for (int r = 0; r < 8; r++) {
            int idx = tid + r * THREADS;
            int row = idx >> 4;
            int d4  = (idx & 15) << 2;
            float4 kk = *(const float4*)(kt + row * DD + d4);
            float* kd = Ks + row * KS_STRIDE + d4;
            kd[0] = kk.x; kd[1] = kk.y; kd[2] = kk.z; kd[3] = kk.w;
            float4 vv = *(const float4*)(vt + row * DD + d4);
            *(float4*)(Vs + row * VS_STRIDE + d4) = vv;
        }
        __syncthreads();

        // ---- S = Q K^T * scale ----
        float s[TM][TN];
        #pragma unroll
        for (int i = 0; i < TM; i++)
            #pragma unroll
            for (int j = 0; j < TN; j++) s[i][j] = 0.0f;

        #pragma unroll 8
        for (int d = 0; d < DD; d++) {
            float qv[TM], kv[TN];
            #pragma unroll
            for (int i = 0; i < TM; i++) qv[i] = Qs[(ty * TM + i) * QS_STRIDE + d];
            #pragma unroll
            for (int j = 0; j < TN; j++) kv[j] = Ks[(tx + j * 8) * KS_STRIDE + d];
            #pragma unroll
            for (int i = 0; i < TM; i++)
                #pragma unroll
                for (int j = 0; j < TN; j++)
                    s[i][j] = fmaf(qv[i], kv[j], s[i][j]);
        }
        const float scale = 0.125f;  // 1/sqrt(64)
        #pragma unroll
        for (int i = 0; i < TM; i++)
            #pragma unroll
            for (int j = 0; j < TN; j++) s[i][j] *= scale;

        // ---- dmat fragment (global, L2-resident across heads) ----
        float dm[TM][TN];
        #pragma unroll
        for (int i = 0; i < TM; i++) {
            const float* drow = db + (size_t)(ty * TM + i) * N_ + t * BN + tx;
            #pragma unroll
            for (int j = 0; j < TN; j++) dm[i][j] = drow[j * 8];
        }

        // ---- per-head MLP: acc = b2 + sum_f w2[f]*relu(w1s[f]*s + w1d[f]*dm + b1[f]) ----
        float acc[TM][TN];
        {
            float c0 = sB2;
            #pragma unroll
            for (int i = 0; i < TM; i++)
                #pragma unroll
                for (int j = 0; j < TN; j++) acc[i][j] = c0;
        }
        #pragma unroll
        for (int f = 0; f < HID; f++) {
            float a = sW1s[f], c = sW1d[f], e = sB1[f], w = sW2[f];
            #pragma unroll
            for (int i = 0; i < TM; i++)
                #pragma unroll
                for (int j = 0; j < TN; j++) {
                    float tv = fmaf(a, s[i][j], fmaf(c, dm[i][j], e));
                    tv = fmaxf(tv, 0.0f);
                    acc[i][j] = fmaf(w, tv, acc[i][j]);
                }
        }

        // ---- online softmax over this tile; write P to smem ----
        #pragma unroll
        for (int i = 0; i < TM; i++) {
            float mx = acc[i][0];
            #pragma unroll
            for (int j = 1; j < TN; j++) mx = fmaxf(mx, acc[i][j]);
            mx = fmaxf(mx, __shfl_xor_sync(FULL, mx, 1, 8));
            mx = fmaxf(mx, __shfl_xor_sync(FULL, mx, 2, 8));
            mx = fmaxf(mx, __shfl_xor_sync(FULL, mx, 4, 8));

            float nm = fmaxf(rmax[i], mx);
            float corr = __expf(rmax[i] - nm);
            rmax[i] = nm;

            float ls = 0.0f;
            #pragma unroll
            for (int j = 0; j < TN; j++) {
                float p = __expf(acc[i][j] - nm);
                acc[i][j] = p;
                ls += p;
            }
            ls += __shfl_xor_sync(FULL, ls, 1, 8);
            ls += __shfl_xor_sync(FULL, ls, 2, 8);
            ls += __shfl_xor_sync(FULL, ls, 4, 8);

            rsum[i] = rsum[i] * corr + ls;
            #pragma unroll
            for (int j = 0; j < TN; j++) Oacc[i][j] *= corr;

            float* prow = Ps + (ty * TM + i) * PS_STRIDE + tx;
            #pragma unroll
            for (int j = 0; j < TN; j++) prow[j * 8] = acc[i][j];
        }
        __syncthreads();

        // ---- O += P @ V ----
        #pragma unroll 8
        for (int n = 0; n < BN; n++) {
            float pv[TM], vv[TN];
            #pragma unroll
            for (int i = 0; i < TM; i++) pv[i] = Ps[(ty * TM + i) * PS_STRIDE + n];
            #pragma unroll
            for (int j = 0; j < TN; j++) vv[j] = Vs[n * VS_STRIDE + tx + j * 8];
            #pragma unroll
            for (int i = 0; i < TM; i++)
                #pragma unroll
                for (int j = 0; j < TN; j++)
                    Oacc[i][j] = fmaf(pv[i], vv[j], Oacc[i][j]);
        }
        __syncthreads();  // before next tile overwrites Ks/Vs/Ps
    }

    // ---- normalize + store ----
    float* ob = out + ((size_t)(b * H_ + h) * M_ + m0) * DD;
    #pragma unroll
    for (int i = 0; i < TM; i++) {
        float inv = 1.0f / rsum[i];
        float* orow = ob + (size_t)(ty * TM + i) * DD + tx;
        #pragma unroll
        for (int j = 0; j < TN; j++) orow[j * 8] = Oacc[i][j] * inv;
    }
}

extern "C" void kernel_launch(void* const* d_in, const int* in_sizes, int n_in,
                              void* d_out, int out_size)
{
    const float* q     = (const float*)d_in[0];
    const float* k     = (const float*)d_in[1];
    const float* v     = (const float*)d_in[2];
    const float* dmat  = (const float*)d_in[3];
    const float* mixW1 = (const float*)d_in[4];
    const float* mixb1 = (const float*)d_in[5];
    const float* mixW2 = (const float*)d_in[6];
    const float* mixb2 = (const float*)d_in[7];
    float* out = (float*)d_out;

    size_t smem_bytes = (size_t)(BM * QS_STRIDE + BN * KS_STRIDE +
                                 BN * VS_STRIDE + BM * PS_STRIDE) * sizeof(float);
    cudaFuncSetAttribute(msdpa_kernel,
                         cudaFuncAttributeMaxDynamicSharedMemorySize,
                         (int)smem_bytes);

    dim3 grid(M_ / BM, H_, B_);   // (8, 8, 8)
    msdpa_kernel<<<grid, THREADS, smem_bytes>>>(q, k, v, dmat,
                                                mixW1, mixb1, mixW2, mixb2, out);
}

// round 2
// speedup vs baseline: 1.1579x; 1.1579x over previous
#include <cuda_runtime.h>
#include <math_constants.h>

#define B_  8
#define H_  8
#define M_  512
#define N_  512
#define DD  64
#define HID 16

#define BM 64
#define BN 64
#define TM 4
#define TN 8
#define THREADS 128

// smem strides (words)
#define QS 68   // 16B-aligned rows, 68%32=4 -> kv/qv LDS.128 near-conflict-free
#define KS 68
#define VS 68
#define PS 70   // scalar access pattern conflict-free for P write + pv read

typedef unsigned long long ull;

__device__ __forceinline__ ull fma2(ull a, ull b, ull c) {
    ull d; asm("fma.rn.f32x2 %0,%1,%2,%3;" : "=l"(d) : "l"(a), "l"(b), "l"(c)); return d;
}
__device__ __forceinline__ ull mul2(ull a, ull b) {
    ull d; asm("mul.rn.f32x2 %0,%1,%2;" : "=l"(d) : "l"(a), "l"(b)); return d;
}
__device__ __forceinline__ ull pk(float x, float y) {
    ull r; asm("mov.b64 %0,{%1,%2};" : "=l"(r) : "f"(x), "f"(y)); return r;
}
__device__ __forceinline__ void upk(ull a, float& x, float& y) {
    asm("mov.b64 {%0,%1},%2;" : "=f"(x), "=f"(y) : "l"(a));
}
__device__ __forceinline__ ull relu2(ull a) {
    float x, y; upk(a, x, y);
    x = fmaxf(x, 0.0f); y = fmaxf(y, 0.0f);
    return pk(x, y);
}

__global__ __launch_bounds__(THREADS, 2)
void msdpa_kernel(const float* __restrict__ q,
                  const float* __restrict__ k,
                  const float* __restrict__ v,
                  const float* __restrict__ dmat,
                  const float* __restrict__ mixW1,
                  const float* __restrict__ mixb1,
                  const float* __restrict__ mixW2,
                  const float* __restrict__ mixb2,
                  float* __restrict__ out)
{
    extern __shared__ float smem[];
    float* Qs = smem;                 // [BM][QS]
    float* Ks = Qs + BM * QS;         // [BN][KS]
    float* Vs = Ks + BN * KS;         // [BN][VS]
    float* Ps = Vs + BN * VS;         // [BM][PS]

    // packed MLP weights: [f][0:1]=w1s*scale dup, [2:3]=w1d dup, [4:5]=b1 dup, [6:7]=w2 dup
    __shared__ __align__(16) float sWp[HID * 8];
    __shared__ float sB2;

    const int tid = threadIdx.x;
    const int tx  = tid & 7;      // 0..7
    const int ty  = tid >> 3;     // 0..15

    const int b  = blockIdx.z;
    const int h  = blockIdx.y;
    const int m0 = blockIdx.x * BM;

    const float* qb = q + ((size_t)(b * H_ + h) * M_ + m0) * DD;
    const float* kb = k + (size_t)(b * H_ + h) * N_ * DD;
    const float* vb = v + (size_t)(b * H_ + h) * N_ * DD;
    const float* db = dmat + ((size_t)b * M_ + m0) * N_;

    if (tid < HID) {
        const float scale = 0.125f;   // 1/sqrt(64), folded into score-channel W1
        float a = mixW1[(h * 2 + 0) * HID + tid] * scale;
        float c = mixW1[(h * 2 + 1) * HID + tid];
        float e = mixb1[h * HID + tid];
        float w = mixW2[h * HID + tid];
        float* wp = sWp + tid * 8;
        wp[0] = a; wp[1] = a;
        wp[2] = c; wp[3] = c;
        wp[4] = e; wp[5] = e;
        wp[6] = w; wp[7] = w;
    }
    if (tid == 0) sB2 = mixb2[h];

    // Load Q tile [BM][DD] -> Qs
    #pragma unroll
    for (int r = 0; r < 8; r++) {
        int idx = tid + r * THREADS;
        int row = idx >> 4;
        int d4  = (idx & 15) << 2;
        float4 t = *(const float4*)(qb + row * DD + d4);
        *(float4*)(Qs + row * QS + d4) = t;
    }

    // accumulators: O packed over adjacent output-col pairs (cols 2*tx + 16*j2 + {0,1})
    ull Oacc2[TM][4];
    float rmax[TM], rsum[TM];
    #pragma unroll
    for (int i = 0; i < TM; i++) {
        rmax[i] = -CUDART_INF_F;
        rsum[i] = 0.0f;
        #pragma unroll
        for (int j2 = 0; j2 < 4; j2++) Oacc2[i][j2] = 0ull;
    }

    __syncthreads();

    const unsigned FULL = 0xffffffffu;
    const float B2 = sB2;

    for (int t = 0; t < N_ / BN; t++) {
        // ---- stage K, V tiles ----
        const float* kt = kb + (size_t)t * BN * DD;
        const float* vt = vb + (size_t)t * BN * DD;
        #pragma unroll
        for (int r = 0; r < 8; r++) {
            int idx = tid + r * THREADS;
            int row = idx >> 4;
            int d4  = (idx & 15) << 2;
            *(float4*)(Ks + row * KS + d4) = *(const float4*)(kt + row * DD + d4);
            *(float4*)(Vs + row * VS + d4) = *(const float4*)(vt + row * DD + d4);
        }
        __syncthreads();

        // ---- S = Q K^T, accumulated in d-parity pairs (FFMA2) ----
        // S cols for this thread: tx + 8*j
        ull s2[TM][TN];
        #pragma unroll
        for (int i = 0; i < TM; i++)
            #pragma unroll
            for (int j = 0; j < TN; j++) s2[i][j] = 0ull;

        #pragma unroll 4
        for (int d4 = 0; d4 < DD; d4 += 4) {
            ulonglong2 qv[TM], kv[TN];
            #pragma unroll
            for (int i = 0; i < TM; i++)
                qv[i] = *(const ulonglong2*)(Qs + (ty * TM + i) * QS + d4);
            #pragma unroll
            for (int j = 0; j < TN; j++)
                kv[j] = *(const ulonglong2*)(Ks + (tx + 8 * j) * KS + d4);
            #pragma unroll
            for (int i = 0; i < TM; i++)
                #pragma unroll
                for (int j = 0; j < TN; j++) {
                    s2[i][j] = fma2(qv[i].x, kv[j].x, s2[i][j]);
                    s2[i][j] = fma2(qv[i].y, kv[j].y, s2[i][j]);
                }
        }

        // ---- reduce pairs, fetch dmat, run packed MLP (cols paired (j,j+1)) ----
        ull ms2[TM][4], dm2[TM][4], acc2[TM][4];
        const ull b2p = pk(B2, B2);
        #pragma unroll
        for (int i = 0; i < TM; i++) {
            #pragma unroll
            for (int j2 = 0; j2 < 4; j2++) {
                float x0, y0, x1, y1;
                upk(s2[i][2 * j2],     x0, y0);
                upk(s2[i][2 * j2 + 1], x1, y1);
                ms2[i][j2] = pk(x0 + y0, x1 + y1);   // raw score (scale folded in W1)
            }
            const float* drow = db + (size_t)(ty * TM + i) * N_ + t * BN + tx;
            #pragma unroll
            for (int j2 = 0; j2 < 4; j2++)
                dm2[i][j2] = pk(drow[(2 * j2) * 8], drow[(2 * j2 + 1) * 8]);
            #pragma unroll
            for (int j2 = 0; j2 < 4; j2++) acc2[i][j2] = b2p;
        }

        #pragma unroll 4
        for (int f = 0; f < HID; f++) {
            const ull a2 = *(const ull*)(sWp + f * 8 + 0);
            const ull c2 = *(const ull*)(sWp + f * 8 + 2);
            const ull e2 = *(const ull*)(sWp + f * 8 + 4);
            const ull w2 = *(const ull*)(sWp + f * 8 + 6);
            #pragma unroll
            for (int i = 0; i < TM; i++)
                #pragma unroll
                for (int j2 = 0; j2 < 4; j2++) {
                    ull t2 = fma2(a2, ms2[i][j2], fma2(c2, dm2[i][j2], e2));
                    acc2[i][j2] = fma2(w2, relu2(t2), acc2[i][j2]);
                }
        }

        // ---- online softmax per row; write P ----
        #pragma unroll
        for (int i = 0; i < TM; i++) {
            float p[TN];
            #pragma unroll
            for (int j2 = 0; j2 < 4; j2++)
                upk(acc2[i][j2], p[2 * j2], p[2 * j2 + 1]);

            float mx = p[0];
            #pragma unroll
            for (int j = 1; j < TN; j++) mx = fmaxf(mx, p[j]);
            mx = fmaxf(mx, __shfl_xor_sync(FULL, mx, 1, 8));
            mx = fmaxf(mx, __shfl_xor_sync(FULL, mx, 2, 8));
            mx = fmaxf(mx, __shfl_xor_sync(FULL, mx, 4, 8));

            float nm   = fmaxf(rmax[i], mx);
            float corr = __expf(rmax[i] - nm);
            rmax[i] = nm;

            float ls = 0.0f;
            #pragma unroll
            for (int j = 0; j < TN; j++) {
                p[j] = __expf(p[j] - nm);
                ls += p[j];
            }
            ls += __shfl_xor_sync(FULL, ls, 1, 8);
            ls += __shfl_xor_sync(FULL, ls, 2, 8);
            ls += __shfl_xor_sync(FULL, ls, 4, 8);
            rsum[i] = rsum[i] * corr + ls;

            const ull c2 = pk(corr, corr);
            #pragma unroll
            for (int j2 = 0; j2 < 4; j2++)
                Oacc2[i][j2] = mul2(Oacc2[i][j2], c2);

            float* prow = Ps + (ty * TM + i) * PS + tx;
            #pragma unroll
            for (int j = 0; j < TN; j++) prow[j * 8] = p[j];
        }
        __syncthreads();

        // ---- O += P @ V (packed over adjacent V-column pairs) ----
        #pragma unroll 4
        for (int n = 0; n < BN; n++) {
            ull pp[TM];
            #pragma unroll
            for (int i = 0; i < TM; i++) {
                float pv = Ps[(ty * TM + i) * PS + n];
                pp[i] = pk(pv, pv);
            }
            ull vv[4];
            #pragma unroll
            for (int j2 = 0; j2 < 4; j2++)
                vv[j2] = *(const ull*)(Vs + n * VS + tx * 2 + 16 * j2);
            #pragma unroll
            for (int i = 0; i < TM; i++)
                #pragma unroll
                for (int j2 = 0; j2 < 4; j2++)
                    Oacc2[i][j2] = fma2(pp[i], vv[j2], Oacc2[i][j2]);
        }
        __syncthreads();
    }

    // ---- normalize + store (adjacent col pairs -> float2 stores) ----
    float* ob = out + ((size_t)(b * H_ + h) * M_ + m0) * DD;
    #pragma unroll
    for (int i = 0; i < TM; i++) {
        float inv = 1.0f / rsum[i];
        #pragma unroll
        for (int j2 = 0; j2 < 4; j2++) {
            float x, y; upk(Oacc2[i][j2], x, y);
            float2 o = make_float2(x * inv, y * inv);
            *(float2*)(ob + (size_t)(ty * TM + i) * DD + tx * 2 + 16 * j2) = o;
        }
    }
}

extern "C" void kernel_launch(void* const* d_in, const int* in_sizes, int n_in,
                              void* d_out, int out_size)
{
    const float* q     = (const float*)d_in[0];
    const float* k     = (const float*)d_in[1];
    const float* v     = (const float*)d_in[2];
    const float* dmat  = (const float*)d_in[3];
    const float* mixW1 = (const float*)d_in[4];
    const float* mixb1 = (const float*)d_in[5];
    const float* mixW2 = (const float*)d_in[6];
    const float* mixb2 = (const float*)d_in[7];
    float* out = (float*)d_out;

    size_t smem_bytes = (size_t)(BM * QS + BN * KS + BN * VS + BM * PS) * sizeof(float);
    cudaFuncSetAttribute(msdpa_kernel,
                         cudaFuncAttributeMaxDynamicSharedMemorySize,
                         (int)smem_bytes);

    dim3 grid(M_ / BM, H_, B_);   // (8, 8, 8)
    msdpa_kernel<<<grid, THREADS, smem_bytes>>>(q, k, v, dmat,
                                                mixW1, mixb1, mixW2, mixb2, out);
}